// round 1
// baseline (speedup 1.0000x reference)
#include <cuda_runtime.h>

// LorentzConv1d: x (16, 8192, 64) f32, W (64, 316) f32, b (64) f32 -> out (16, 8192, 64) f32
//
// Per output position l (with L-padding of 2, pad rows have time=1, space=0):
//   t_resc      = sqrt( sum_{k=0..4} time[l-2+k]^2 - 4 )
//   y[o]        = b[o] + W[o,0]*t_resc + sum_{c=1..63,k=0..4} W[o,(c-1)*5+1+k] * x[l-2+k, c]
//   out[l,0]    = sqrt( sum_{o=1..63} y[o]^2 + 1 )
//   out[l,o>=1] = y[o]
// (y[0] from the GEMM is discarded by the reference, so it is excluded from the norm.)

#define NBATCH   16
#define LLEN     8192
#define CIN      64
#define COUT     64
#define LFEAT    316          // (CIN-1)*5 + 1
#define TL       64           // L-positions per block
#define TILES_PB (LLEN / TL)  // 128
#define WS_STRIDE 66          // padded row stride for W smem (even -> float2 aligned, 2-way fill conflict)
#define XS_STRIDE 69          // padded row stride for x smem (odd -> conflict-free fill)
#define XROWS    68           // TL + 4 halo rows
#define SMEM_FLOATS (LFEAT * WS_STRIDE + CIN * XS_STRIDE)
#define SMEM_BYTES  (SMEM_FLOATS * 4)

__device__ __forceinline__ unsigned long long pack2(float v) {
    unsigned long long r;
    asm("mov.b64 %0, {%1, %1};" : "=l"(r) : "f"(v));
    return r;
}
__device__ __forceinline__ unsigned long long pack2(float lo, float hi) {
    unsigned long long r;
    asm("mov.b64 %0, {%1, %2};" : "=l"(r) : "f"(lo), "f"(hi));
    return r;
}
__device__ __forceinline__ void unpack2(unsigned long long v, float& lo, float& hi) {
    asm("mov.b64 {%0, %1}, %2;" : "=f"(lo), "=f"(hi) : "l"(v));
}
__device__ __forceinline__ void fma2(unsigned long long& d,
                                     unsigned long long a, unsigned long long b) {
    asm("fma.rn.f32x2 %0, %1, %2, %0;" : "+l"(d) : "l"(a), "l"(b));
}

__global__ __launch_bounds__(256, 2)
void lorentz_conv1d_kernel(const float* __restrict__ x,
                           const float* __restrict__ W,
                           const float* __restrict__ bvec,
                           float* __restrict__ out)
{
    extern __shared__ float smem[];
    float* ws = smem;                          // [LFEAT][WS_STRIDE], ws[f*66 + o]
    float* xs = smem + LFEAT * WS_STRIDE;      // [CIN][XS_STRIDE],  xs[c*69 + localrow]

    const int b   = blockIdx.x >> 7;           // TILES_PB = 128
    const int l0  = (blockIdx.x & (TILES_PB - 1)) * TL;
    const int tid = threadIdx.y * 32 + threadIdx.x;

    // ---- stage W transposed: ws[f][o] = W[o][f] ----
    for (int idx = tid; idx < COUT * LFEAT; idx += 256) {
        int o = idx / LFEAT;
        int f = idx - o * LFEAT;
        ws[f * WS_STRIDE + o] = W[idx];
    }

    // ---- stage x tile: rows l0-2 .. l0+65, channel-major ----
    const float* xb = x + (size_t)b * (LLEN * CIN);
    for (int idx = tid; idx < XROWS * CIN; idx += 256) {
        int row  = idx >> 6;       // 0..67
        int c    = idx & 63;
        int grow = l0 - 2 + row;
        float v  = (c == 0) ? 1.0f : 0.0f;     // pad: time=sqrt(K)=1, space=0
        if ((unsigned)grow < (unsigned)LLEN) v = xb[grow * CIN + c];
        xs[c * XS_STRIDE + row] = v;
    }
    __syncthreads();

    const int lane  = threadIdx.x;             // owns output channels {2*lane, 2*lane+1}
    const int pbase = threadIdx.y * 8;         // 8 contiguous local positions per thread

    // ---- t_resc per position (time channel = xs row 0..) ----
    float tre[8];
#pragma unroll
    for (int r = 0; r < 8; r++) {
        float s = -4.0f;                       // -(KERNEL-1)*K_CURV
#pragma unroll
        for (int j = 0; j < 5; j++) {
            float t = xs[pbase + r + j];       // channel 0 base offset = 0
            s = fmaf(t, t, s);
        }
        tre[r] = sqrtf(s);
    }

    // ---- init accumulators: b + W[:,0] * t_resc ----
    unsigned long long acc[8];
    {
        const float2 bp = *(const float2*)(bvec + 2 * lane);
        const float2 w0 = *(const float2*)(ws + 2 * lane);  // f = 0 row
#pragma unroll
        for (int r = 0; r < 8; r++) {
            acc[r] = pack2(fmaf(w0.x, tre[r], bp.x),
                           fmaf(w0.y, tre[r], bp.y));
        }
    }

    // ---- main loop: c = 1..63, k = 0..4, packed f32x2 FMA over output-channel pairs ----
    for (int c = 1; c < CIN; c++) {
        const float* xc = xs + c * XS_STRIDE + pbase;
        unsigned long long xp[12];             // rows pbase .. pbase+11 (8 positions + 4 halo)
#pragma unroll
        for (int j = 0; j < 12; j++) xp[j] = pack2(xc[j]);  // broadcast LDS

        const float* wf = ws + ((c - 1) * 5 + 1) * WS_STRIDE + 2 * lane;
#pragma unroll
        for (int k = 0; k < 5; k++) {
            unsigned long long w2 = *(const unsigned long long*)(wf + k * WS_STRIDE);
#pragma unroll
            for (int r = 0; r < 8; r++) {
                fma2(acc[r], w2, xp[r + k]);
            }
        }
    }

    // ---- epilogue: Lorentz time norm over o=1..63, store ----
    const size_t obase = ((size_t)b * LLEN + (size_t)(l0 + pbase)) * COUT;
#pragma unroll
    for (int r = 0; r < 8; r++) {
        float y0, y1;
        unpack2(acc[r], y0, y1);
        float ss = y1 * y1;
        if (lane != 0) ss = fmaf(y0, y0, ss);  // exclude discarded y[0]
#pragma unroll
        for (int m = 16; m > 0; m >>= 1) ss += __shfl_xor_sync(0xffffffffu, ss, m);
        float out0 = y0;
        if (lane == 0) out0 = sqrtf(ss + 1.0f);
        float2 ov = make_float2(out0, y1);
        *(float2*)(out + obase + (size_t)r * COUT + 2 * lane) = ov;
    }
}

extern "C" void kernel_launch(void* const* d_in, const int* in_sizes, int n_in,
                              void* d_out, int out_size)
{
    const float* x = (const float*)d_in[0];
    const float* W = (const float*)d_in[1];
    const float* b = (const float*)d_in[2];
    float* out = (float*)d_out;

    cudaFuncSetAttribute(lorentz_conv1d_kernel,
                         cudaFuncAttributeMaxDynamicSharedMemorySize, SMEM_BYTES);

    dim3 blk(32, 8);
    dim3 grd(NBATCH * TILES_PB);
    lorentz_conv1d_kernel<<<grd, blk, SMEM_BYTES>>>(x, W, b, out);
}

// round 3
// speedup vs baseline: 1.3690x; 1.3690x over previous
#include <cuda_runtime.h>
#include <cuda_bf16.h>
#include <cstdint>

// LorentzConv1d via warp-level mma.sync (bf16 hi/lo 3-chain split, fp32 accum).
//   y[m,o] = b[o] + W[o,0]*t_resc(m) + sum_{f'=0..314} feats[m,f'] * W[o,1+f']
//   feats[m,f'] = x[m-2+k, c],  c = f'/5+1, k = f'%5   (pad rows: space=0, time=1)
//   t_resc(m)   = sqrt(sum_{k=0..4} time[m-2+k]^2 - 4)
//   out[m,0]    = sqrt(sum_{o>=1} y[m,o]^2 + 1),  out[m,o>=1] = y[m,o]
//
// GEMM K padded 315->320 (zeros both sides). M=128/CTA, 8 warps x 16 rows.
// x staged in smem as packed (bf16_hi | bf16_lo<<16); A fragments built in regs.
// W staged as fragment-ordered 8B units, hi & lo tiles, conflict-free banks.

#define LLEN 8192
#define CIN  64
#define XSTR 68                  // xs row stride in words (4-word aligned, bank stride 4)
#define XROWS 132
#define XS_WORDS (XROWS * XSTR)  // 8976
#define TR_OFF   XS_WORDS        // 128 floats
#define WB4_OFF  (TR_OFF + 128)  // 32 float4 = 128 words (16B aligned: 9104*4)
#define BH_OFF   (WB4_OFF + 128) // 9232
#define BS_ROW   162             // words per n-row (640B data + 8B pad)
#define BS_WORDS (64 * BS_ROW)   // 10368
#define BL_OFF   (BH_OFF + BS_WORDS)
#define SMEM_WORDS (BL_OFF + BS_WORDS)   // 29968
#define SMEM_BYTES (SMEM_WORDS * 4)      // 119872

__device__ __forceinline__ uint32_t pack_hilo(float v) {
    __nv_bfloat16 h = __float2bfloat16_rn(v);
    float hf = __bfloat162float(h);
    __nv_bfloat16 l = __float2bfloat16_rn(v - hf);
    return (uint32_t)__bfloat16_as_ushort(h) | ((uint32_t)__bfloat16_as_ushort(l) << 16);
}
__device__ __forceinline__ float unpack_sum(uint32_t w) {
    float h = __bfloat162float(__ushort_as_bfloat16((unsigned short)(w & 0xffffu)));
    float l = __bfloat162float(__ushort_as_bfloat16((unsigned short)(w >> 16)));
    return h + l;
}
__device__ __forceinline__ void hilo_bits(float v, uint32_t& h, uint32_t& l) {
    __nv_bfloat16 hb = __float2bfloat16_rn(v);
    h = (uint32_t)__bfloat16_as_ushort(hb);
    l = (uint32_t)__bfloat16_as_ushort(__float2bfloat16_rn(v - __bfloat162float(hb)));
}
__device__ __forceinline__ void mma_bf16(float* d, const uint32_t* a, uint2 b) {
    asm volatile(
        "mma.sync.aligned.m16n8k16.row.col.f32.bf16.bf16.f32 "
        "{%0,%1,%2,%3}, {%4,%5,%6,%7}, {%8,%9}, {%0,%1,%2,%3};"
        : "+f"(d[0]), "+f"(d[1]), "+f"(d[2]), "+f"(d[3])
        : "r"(a[0]), "r"(a[1]), "r"(a[2]), "r"(a[3]), "r"(b.x), "r"(b.y));
}

__global__ __launch_bounds__(256, 1)
void lorentz_mma_kernel(const float* __restrict__ x,
                        const float* __restrict__ W,
                        const float* __restrict__ bvec,
                        float* __restrict__ out)
{
    extern __shared__ uint32_t sm[];
    uint32_t* xs  = sm;
    float*    tr  = (float*)(sm + TR_OFF);
    float4*   wb4 = (float4*)(sm + WB4_OFF);
    uint32_t* Bh  = sm + BH_OFF;
    uint32_t* Bl  = sm + BL_OFF;

    const int tid  = threadIdx.x;
    const int wid  = tid >> 5;
    const int lane = tid & 31;
    const int bidx = blockIdx.x >> 6;
    const int l0   = (blockIdx.x & 63) << 7;

    // ---- stage x tile (rows l0-2 .. l0+129) as packed hi|lo bf16 ----
    const float* xb = x + (size_t)bidx * (LLEN * CIN);
    for (int idx = tid; idx < XROWS * 16; idx += 256) {
        int r = idx >> 4, c4 = idx & 15;
        int g = l0 - 2 + r;
        float4 v;
        if ((unsigned)g < (unsigned)LLEN) v = *(const float4*)(xb + (size_t)g * CIN + c4 * 4);
        else { v = make_float4(0.f, 0.f, 0.f, 0.f); if (c4 == 0) v.x = 1.0f; }
        uint4 p;
        p.x = pack_hilo(v.x); p.y = pack_hilo(v.y);
        p.z = pack_hilo(v.z); p.w = pack_hilo(v.w);
        *(uint4*)(xs + r * XSTR + c4 * 4) = p;
    }

    // ---- stage W fragment-ordered: Bs[n][g][kb] 8B units, hi & lo ----
    for (int u = tid; u < 64 * 80; u += 256) {
        int n  = u / 80;
        int rr = u - n * 80;
        int g  = rr / 20;
        int kb = rr - g * 20;
        int fb = kb * 16 + 2 * g;          // f' of unit's first element
        const float* Wr = W + (size_t)n * 316 + 1;
        float w0 = (fb + 0 < 315) ? Wr[fb + 0] : 0.f;
        float w1 = (fb + 1 < 315) ? Wr[fb + 1] : 0.f;
        float w8 = (fb + 8 < 315) ? Wr[fb + 8] : 0.f;
        float w9 = (fb + 9 < 315) ? Wr[fb + 9] : 0.f;
        uint32_t h0, l0b, h1, l1, h8, l8, h9, l9;
        hilo_bits(w0, h0, l0b); hilo_bits(w1, h1, l1);
        hilo_bits(w8, h8, l8);  hilo_bits(w9, h9, l9);
        int off = n * BS_ROW + g * 40 + kb * 2;
        *(uint2*)(Bh + off) = make_uint2(h0 | (h1 << 16), h8 | (h9 << 16));
        *(uint2*)(Bl + off) = make_uint2(l0b | (l1 << 16), l8 | (l9 << 16));
    }

    // ---- stage fp32 time-weight + bias: wb4[n2] = (W[2n2][0], b[2n2], W[2n2+1][0], b[2n2+1]) ----
    if (tid < 32) {
        wb4[tid] = make_float4(W[(size_t)(2 * tid) * 316], bvec[2 * tid],
                               W[(size_t)(2 * tid + 1) * 316], bvec[2 * tid + 1]);
    }
    __syncthreads();

    // ---- t_resc per output row (fp32 from reconstructed hi+lo) ----
    if (tid < 128) {
        float s = -4.0f;
#pragma unroll
        for (int k = 0; k < 5; k++) {
            float t = unpack_sum(xs[(tid + k) * XSTR]);
            s = fmaf(t, t, s);
        }
        tr[tid] = sqrtf(s);
    }

    // ---- mainloop: per warp 16 rows x 64 cols, K=320, 3 mma chains ----
    const int q4 = lane >> 2;      // 0..7
    const int s4 = lane & 3;       // 0..3
    const int mbase = wid * 16;
    const int rowa = mbase + q4;   // local row of d0/d1

    float d[8][4];
#pragma unroll
    for (int nb = 0; nb < 8; nb++) { d[nb][0] = d[nb][1] = d[nb][2] = d[nb][3] = 0.f; }

#pragma unroll 2
    for (int kb = 0; kb < 20; kb++) {
        const int fb = kb * 16 + 2 * s4;
        uint32_t wa[8];
#pragma unroll
        for (int i = 0; i < 4; i++) {
            int f = fb + ((i & 1) | ((i & 2) << 2));   // +0, +1, +8, +9
            int q = (f * 52429) >> 18;                 // f / 5
            int k = f - 5 * q;
            int c = q + 1;
            int base = (rowa + k) * XSTR + c;
            uint32_t v0 = xs[base];
            uint32_t v1 = xs[base + 8 * XSTR];
            if (f >= 315) { v0 = 0u; v1 = 0u; }
            wa[i] = v0; wa[i + 4] = v1;
        }
        uint32_t ah[4], al[4];
        ah[0] = __byte_perm(wa[0], wa[1], 0x5410);
        ah[1] = __byte_perm(wa[4], wa[5], 0x5410);
        ah[2] = __byte_perm(wa[2], wa[3], 0x5410);
        ah[3] = __byte_perm(wa[6], wa[7], 0x5410);
        al[0] = __byte_perm(wa[0], wa[1], 0x7632);
        al[1] = __byte_perm(wa[4], wa[5], 0x7632);
        al[2] = __byte_perm(wa[2], wa[3], 0x7632);
        al[3] = __byte_perm(wa[6], wa[7], 0x7632);

#pragma unroll
        for (int nb = 0; nb < 8; nb++) {
            int bo = (nb * 8 + q4) * BS_ROW + s4 * 40 + kb * 2;
            uint2 bh = *(const uint2*)(Bh + bo);
            uint2 bl = *(const uint2*)(Bl + bo);
            mma_bf16(d[nb], ah, bh);
            mma_bf16(d[nb], ah, bl);
            mma_bf16(d[nb], al, bh);
        }
    }

    __syncthreads();   // tr written pre-mainloop by all threads; ensure visible

    // ---- epilogue: + W[:,0]*t_resc + b (fp32), Lorentz norm, store ----
    const float tra = tr[rowa];
    const float trb = tr[rowa + 8];
    float ssa = 0.f, ssb = 0.f;
#pragma unroll
    for (int nb = 0; nb < 8; nb++) {
        float4 f4 = wb4[nb * 4 + s4];
        float y0 = fmaf(f4.x, tra, d[nb][0]) + f4.y;
        float y1 = fmaf(f4.z, tra, d[nb][1]) + f4.w;
        float y2 = fmaf(f4.x, trb, d[nb][2]) + f4.y;
        float y3 = fmaf(f4.z, trb, d[nb][3]) + f4.w;
        if (!(nb == 0 && s4 == 0)) {       // n=0 excluded from the norm
            ssa = fmaf(y0, y0, ssa);
            ssb = fmaf(y2, y2, ssb);
        }
        ssa = fmaf(y1, y1, ssa);
        ssb = fmaf(y3, y3, ssb);
        d[nb][0] = y0; d[nb][1] = y1; d[nb][2] = y2; d[nb][3] = y3;
    }
    ssa += __shfl_xor_sync(0xffffffffu, ssa, 1);
    ssa += __shfl_xor_sync(0xffffffffu, ssa, 2);
    ssb += __shfl_xor_sync(0xffffffffu, ssb, 1);
    ssb += __shfl_xor_sync(0xffffffffu, ssb, 2);
    if (s4 == 0) {
        d[0][0] = sqrtf(ssa + 1.0f);
        d[0][2] = sqrtf(ssb + 1.0f);
    }

    const size_t oa = ((size_t)bidx * LLEN + (size_t)(l0 + rowa)) * 64 + 2 * s4;
    const size_t ob = oa + 8 * 64;
#pragma unroll
    for (int nb = 0; nb < 8; nb++) {
        *(float2*)(out + oa + nb * 8) = make_float2(d[nb][0], d[nb][1]);
        *(float2*)(out + ob + nb * 8) = make_float2(d[nb][2], d[nb][3]);
    }
}

extern "C" void kernel_launch(void* const* d_in, const int* in_sizes, int n_in,
                              void* d_out, int out_size)
{
    const float* x = (const float*)d_in[0];
    const float* W = (const float*)d_in[1];
    const float* b = (const float*)d_in[2];
    float* out = (float*)d_out;

    cudaFuncSetAttribute(lorentz_mma_kernel,
                         cudaFuncAttributeMaxDynamicSharedMemorySize, SMEM_BYTES);
    lorentz_mma_kernel<<<1024, 256, SMEM_BYTES>>>(x, W, b, out);
}

// round 4
// speedup vs baseline: 1.9621x; 1.4332x over previous
#include <cuda_runtime.h>
#include <cuda_bf16.h>
#include <cstdint>

// LorentzConv1d via warp-level mma.sync (bf16 hi/lo 3-chain split, fp32 accum).
// M=256/CTA, 16 warps x 16 rows, N=64, K=315 padded to 320.
// B tiles interleaved (hi-pair, lo-pair) as 16B units -> one LDS.128 per (nb,kb).

#define LLEN 8192
#define CIN  64
#define MT   256
#define XSTR 68                     // xs row stride in words
#define XROWS 260                   // MT + 4 halo
#define XS_WORDS (XROWS * XSTR)     // 17680
#define TR_OFF   XS_WORDS           // 256 floats
#define WB4_OFF  (TR_OFF + 256)     // 128 words (16B aligned)
#define B_OFF    (WB4_OFF + 128)    // 18064 words (16B aligned)
#define RSU 89                      // B row stride in 16B units (== 1 mod 8)
#define SG  22                      // B s4-group stride in 16B units (== 6 mod 8)
#define B_WORDS  (64 * RSU * 4)     // 22784
#define SMEM_WORDS (B_OFF + B_WORDS)    // 40848
#define SMEM_BYTES (SMEM_WORDS * 4)     // 163392

__device__ __forceinline__ uint32_t pack_hilo(float v) {
    __nv_bfloat16 h = __float2bfloat16_rn(v);
    float hf = __bfloat162float(h);
    __nv_bfloat16 l = __float2bfloat16_rn(v - hf);
    return (uint32_t)__bfloat16_as_ushort(h) | ((uint32_t)__bfloat16_as_ushort(l) << 16);
}
__device__ __forceinline__ float unpack_sum(uint32_t w) {
    float h = __bfloat162float(__ushort_as_bfloat16((unsigned short)(w & 0xffffu)));
    float l = __bfloat162float(__ushort_as_bfloat16((unsigned short)(w >> 16)));
    return h + l;
}
__device__ __forceinline__ void hilo_bits(float v, uint32_t& h, uint32_t& l) {
    __nv_bfloat16 hb = __float2bfloat16_rn(v);
    h = (uint32_t)__bfloat16_as_ushort(hb);
    l = (uint32_t)__bfloat16_as_ushort(__float2bfloat16_rn(v - __bfloat162float(hb)));
}
__device__ __forceinline__ void mma_bf16(float* d, const uint32_t* a, uint32_t b0, uint32_t b1) {
    asm volatile(
        "mma.sync.aligned.m16n8k16.row.col.f32.bf16.bf16.f32 "
        "{%0,%1,%2,%3}, {%4,%5,%6,%7}, {%8,%9}, {%0,%1,%2,%3};"
        : "+f"(d[0]), "+f"(d[1]), "+f"(d[2]), "+f"(d[3])
        : "r"(a[0]), "r"(a[1]), "r"(a[2]), "r"(a[3]), "r"(b0), "r"(b1));
}

__global__ __launch_bounds__(512, 1)
void lorentz_mma_kernel(const float* __restrict__ x,
                        const float* __restrict__ W,
                        const float* __restrict__ bvec,
                        float* __restrict__ out)
{
    extern __shared__ uint32_t sm[];
    uint32_t* xs  = sm;
    float*    tr  = (float*)(sm + TR_OFF);
    float4*   wb4 = (float4*)(sm + WB4_OFF);
    uint4*    Bq  = (uint4*)(sm + B_OFF);

    const int tid  = threadIdx.x;
    const int wid  = tid >> 5;
    const int lane = tid & 31;
    const int bidx = blockIdx.x >> 5;          // 32 tiles per batch
    const int l0   = (blockIdx.x & 31) << 8;   // 256 rows per tile

    // ---- stage x tile (rows l0-2 .. l0+257) as packed hi|lo bf16 ----
    const float* xb = x + (size_t)bidx * (LLEN * CIN);
    for (int idx = tid; idx < XROWS * 16; idx += 512) {
        int r = idx >> 4, c4 = idx & 15;
        int g = l0 - 2 + r;
        float4 v;
        if ((unsigned)g < (unsigned)LLEN) v = *(const float4*)(xb + (size_t)g * CIN + c4 * 4);
        else { v = make_float4(0.f, 0.f, 0.f, 0.f); if (c4 == 0) v.x = 1.0f; }
        uint4 p;
        p.x = pack_hilo(v.x); p.y = pack_hilo(v.y);
        p.z = pack_hilo(v.z); p.w = pack_hilo(v.w);
        *(uint4*)(xs + r * XSTR + c4 * 4) = p;
    }

    // ---- stage W: interleaved (hi-pair, lo-pair) 16B units, fragment order ----
    for (int u = tid; u < 64 * 80; u += 512) {
        int n  = u / 80;
        int rr = u - n * 80;
        int g  = rr / 20;
        int kb = rr - g * 20;
        int fb = kb * 16 + 2 * g;
        const float* Wr = W + (size_t)n * 316 + 1;
        float w0 = (fb + 0 < 315) ? Wr[fb + 0] : 0.f;
        float w1 = (fb + 1 < 315) ? Wr[fb + 1] : 0.f;
        float w8 = (fb + 8 < 315) ? Wr[fb + 8] : 0.f;
        float w9 = (fb + 9 < 315) ? Wr[fb + 9] : 0.f;
        uint32_t h0, l0b, h1, l1, h8, l8, h9, l9;
        hilo_bits(w0, h0, l0b); hilo_bits(w1, h1, l1);
        hilo_bits(w8, h8, l8);  hilo_bits(w9, h9, l9);
        Bq[n * RSU + g * SG + kb] =
            make_uint4(h0 | (h1 << 16), h8 | (h9 << 16),
                       l0b | (l1 << 16), l8 | (l9 << 16));
    }

    // ---- fp32 time-weight + bias pairs ----
    if (tid < 32) {
        wb4[tid] = make_float4(W[(size_t)(2 * tid) * 316], bvec[2 * tid],
                               W[(size_t)(2 * tid + 1) * 316], bvec[2 * tid + 1]);
    }
    __syncthreads();

    // ---- t_resc per row ----
    if (tid < MT) {
        float s = -4.0f;
#pragma unroll
        for (int k = 0; k < 5; k++) {
            float t = unpack_sum(xs[(tid + k) * XSTR]);
            s = fmaf(t, t, s);
        }
        tr[tid] = sqrtf(s);
    }

    // ---- mainloop ----
    const int q4 = lane >> 2;
    const int s4 = lane & 3;
    const int rowa = wid * 16 + q4;

    float d[8][4];
#pragma unroll
    for (int nb = 0; nb < 8; nb++) { d[nb][0] = d[nb][1] = d[nb][2] = d[nb][3] = 0.f; }

#define KB_BODY(KB, MASKED)                                                     \
    {                                                                           \
        const int fb = (KB) * 16 + 2 * s4;                                      \
        uint32_t wa[8];                                                         \
        _Pragma("unroll")                                                       \
        for (int i = 0; i < 4; i++) {                                           \
            int f = fb + ((i & 1) | ((i & 2) << 2));                            \
            int q = (f * 52429) >> 18;                                          \
            int k = f - 5 * q;                                                  \
            int c = q + 1;                                                      \
            int base = (rowa + k) * XSTR + c;                                   \
            uint32_t v0 = xs[base];                                             \
            uint32_t v1 = xs[base + 8 * XSTR];                                  \
            if (MASKED && f >= 315) { v0 = 0u; v1 = 0u; }                       \
            wa[i] = v0; wa[i + 4] = v1;                                         \
        }                                                                       \
        uint32_t ah[4], al[4];                                                  \
        ah[0] = __byte_perm(wa[0], wa[1], 0x5410);                              \
        ah[1] = __byte_perm(wa[4], wa[5], 0x5410);                              \
        ah[2] = __byte_perm(wa[2], wa[3], 0x5410);                              \
        ah[3] = __byte_perm(wa[6], wa[7], 0x5410);                              \
        al[0] = __byte_perm(wa[0], wa[1], 0x7632);                              \
        al[1] = __byte_perm(wa[4], wa[5], 0x7632);                              \
        al[2] = __byte_perm(wa[2], wa[3], 0x7632);                              \
        al[3] = __byte_perm(wa[6], wa[7], 0x7632);                              \
        _Pragma("unroll")                                                       \
        for (int nb = 0; nb < 8; nb++) {                                        \
            uint4 bb = Bq[(nb * 8 + q4) * RSU + s4 * SG + (KB)];                \
            mma_bf16(d[nb], ah, bb.x, bb.y);                                    \
            mma_bf16(d[nb], ah, bb.z, bb.w);                                    \
            mma_bf16(d[nb], al, bb.x, bb.y);                                    \
        }                                                                       \
    }

#pragma unroll
    for (int kb = 0; kb < 19; kb++) KB_BODY(kb, false)
    KB_BODY(19, true)

    __syncthreads();

    // ---- epilogue: + W[:,0]*t_resc + b, Lorentz norm, store ----
    const float tra = tr[rowa];
    const float trb = tr[rowa + 8];
    float ssa = 0.f, ssb = 0.f;
#pragma unroll
    for (int nb = 0; nb < 8; nb++) {
        float4 f4 = wb4[nb * 4 + s4];
        float y0 = fmaf(f4.x, tra, d[nb][0]) + f4.y;
        float y1 = fmaf(f4.z, tra, d[nb][1]) + f4.w;
        float y2 = fmaf(f4.x, trb, d[nb][2]) + f4.y;
        float y3 = fmaf(f4.z, trb, d[nb][3]) + f4.w;
        if (!(nb == 0 && s4 == 0)) {         // col 0 excluded from the norm
            ssa = fmaf(y0, y0, ssa);
            ssb = fmaf(y2, y2, ssb);
        }
        ssa = fmaf(y1, y1, ssa);
        ssb = fmaf(y3, y3, ssb);
        d[nb][0] = y0; d[nb][1] = y1; d[nb][2] = y2; d[nb][3] = y3;
    }
    ssa += __shfl_xor_sync(0xffffffffu, ssa, 1);
    ssa += __shfl_xor_sync(0xffffffffu, ssa, 2);
    ssb += __shfl_xor_sync(0xffffffffu, ssb, 1);
    ssb += __shfl_xor_sync(0xffffffffu, ssb, 2);
    if (s4 == 0) {
        d[0][0] = sqrtf(ssa + 1.0f);
        d[0][2] = sqrtf(ssb + 1.0f);
    }

    const size_t oa = ((size_t)bidx * LLEN + (size_t)(l0 + rowa)) * 64 + 2 * s4;
    const size_t ob = oa + 8 * 64;
#pragma unroll
    for (int nb = 0; nb < 8; nb++) {
        *(float2*)(out + oa + nb * 8) = make_float2(d[nb][0], d[nb][1]);
        *(float2*)(out + ob + nb * 8) = make_float2(d[nb][2], d[nb][3]);
    }
}

extern "C" void kernel_launch(void* const* d_in, const int* in_sizes, int n_in,
                              void* d_out, int out_size)
{
    const float* x = (const float*)d_in[0];
    const float* W = (const float*)d_in[1];
    const float* b = (const float*)d_in[2];
    float* out = (float*)d_out;

    cudaFuncSetAttribute(lorentz_mma_kernel,
                         cudaFuncAttributeMaxDynamicSharedMemorySize, SMEM_BYTES);
    lorentz_mma_kernel<<<512, 512, SMEM_BYTES>>>(x, W, b, out);
}

// round 5
// speedup vs baseline: 2.4234x; 1.2351x over previous
#include <cuda_runtime.h>
#include <cuda_fp16.h>
#include <cstdint>

// LorentzConv1d via single-pass fp16 mma.sync m16n8k16 (fp32 accum).
// GEMM K permuted into 160 pairs so every mma k-pair is one aligned LDS.32:
//   pairs 0..125 : channel c=1..63, taps (0,1) and (2,3) -> xp row-pair tile
//   pairs 126..157: tap 4, channels (2j, 2j+1), j=0..31  -> xr row-major tile
//   pairs 158..159: zero padding (B=0, A reads a zero word)
// t_resc handled as fp32 rank-1 epilogue term (W[:,0] * t_resc + b).

#define LLEN 8192
#define CIN  64
#define MT   256
#define XPS  68                       // xp row stride (words)
#define XRS  34                       // xr row stride (words)
#define NR   260                      // staged rows (MT + 4 halo)
#define XP_OFF  0
#define XR_OFF  (NR * XPS)            // 17680
#define TR_OFF  (XR_OFF + NR * XRS)   // 26520
#define WB4_OFF (TR_OFF + 256)        // 26776 (16B aligned)
#define ZW_OFF  (WB4_OFF + 128)       // 26904
#define B_OFF   (ZW_OFF + 8)          // 26912 (8B aligned)
#define B_LG_STRIDE 162               // uint2 units per lane-group (20*8 + 2 pad)
#define SMEM_WORDS (B_OFF + 32 * B_LG_STRIDE * 2)   // 37280
#define SMEM_BYTES (SMEM_WORDS * 4)                 // 149120

__device__ __forceinline__ uint32_t h2pack(float a, float b) {
    __half2 h = __floats2half2_rn(a, b);
    return *(uint32_t*)&h;
}
__device__ __forceinline__ void mma_f16(float* d, const uint32_t* a, uint32_t b0, uint32_t b1) {
    asm volatile(
        "mma.sync.aligned.m16n8k16.row.col.f32.f16.f16.f32 "
        "{%0,%1,%2,%3}, {%4,%5,%6,%7}, {%8,%9}, {%0,%1,%2,%3};"
        : "+f"(d[0]), "+f"(d[1]), "+f"(d[2]), "+f"(d[3])
        : "r"(a[0]), "r"(a[1]), "r"(a[2]), "r"(a[3]), "r"(b0), "r"(b1));
}
// W value for permuted slot s = 2p + t (see header comment)
__device__ __forceinline__ float slotW(const float* __restrict__ Wr, int p, int t) {
    if (p >= 158) return 0.f;
    if (p >= 126) {
        int ch = 2 * (p - 126) + t;
        return (ch == 0) ? 0.f : Wr[(ch - 1) * 5 + 5];
    }
    int c = (p >> 1) + 1;
    int kk = (p & 1) * 2 + t;
    return Wr[(c - 1) * 5 + kk + 1];
}

__global__ __launch_bounds__(512, 1)
void lorentz_f16_kernel(const float* __restrict__ x,
                        const float* __restrict__ W,
                        const float* __restrict__ bvec,
                        float* __restrict__ out)
{
    extern __shared__ uint32_t sm[];
    float*  tr  = (float*)(sm + TR_OFF);
    float4* wb4 = (float4*)(sm + WB4_OFF);
    uint2*  BQ2 = (uint2*)(sm + B_OFF);

    const int tid  = threadIdx.x;
    const int wid  = tid >> 5;
    const int lane = tid & 31;
    const int bidx = blockIdx.x >> 5;          // 32 tiles per batch
    const int l0   = (blockIdx.x & 31) << 8;   // 256 rows per tile

    if (tid < 8) sm[ZW_OFF + tid] = 0;

    // ---- stage xp (row-pair packed fp16) and xr (row-major fp16) ----
    const float* xb = x + (size_t)bidx * (LLEN * CIN);
    for (int idx = tid; idx < NR * 16; idx += 512) {
        int r = idx >> 4, c4 = idx & 15;
        int g = l0 - 2 + r;
        float4 v0, v1;
        if ((unsigned)g < (unsigned)LLEN) v0 = *(const float4*)(xb + (size_t)g * CIN + c4 * 4);
        else { v0 = make_float4(0.f, 0.f, 0.f, 0.f); if (c4 == 0) v0.x = 1.0f; }
        if ((unsigned)(g + 1) < (unsigned)LLEN) v1 = *(const float4*)(xb + (size_t)(g + 1) * CIN + c4 * 4);
        else { v1 = make_float4(0.f, 0.f, 0.f, 0.f); if (c4 == 0) v1.x = 1.0f; }
        uint4 pw;
        pw.x = h2pack(v0.x, v1.x); pw.y = h2pack(v0.y, v1.y);
        pw.z = h2pack(v0.z, v1.z); pw.w = h2pack(v0.w, v1.w);
        *(uint4*)(sm + XP_OFF + r * XPS + c4 * 4) = pw;
        uint2 rw;
        rw.x = h2pack(v0.x, v0.y); rw.y = h2pack(v0.z, v0.w);
        *(uint2*)(sm + XR_OFF + r * XRS + c4 * 2) = rw;
    }

    // ---- t_resc per output row, exact fp32 from global ----
    if (tid < MT) {
        int g0 = l0 + tid - 2;
        float s = -4.0f;
#pragma unroll
        for (int k = 0; k < 5; k++) {
            int g = g0 + k;
            float t = ((unsigned)g < (unsigned)LLEN) ? xb[(size_t)g * CIN] : 1.0f;
            s = fmaf(t, t, s);
        }
        tr[tid] = sqrtf(s);
    }

    // ---- stage B (fp16, permuted slots, conflict-free lane-group layout) ----
    for (int u = tid; u < 32 * 20 * 8; u += 512) {
        int nb = u & 7;
        int t2 = u >> 3;
        int kb = t2 % 20;
        int lg = t2 / 20;
        int s4g = lg & 3;
        int n = nb * 8 + (lg >> 2);
        const float* Wr = W + (size_t)n * 316;
        int p0 = 8 * kb + s4g, p2 = p0 + 4;
        uint2 w;
        w.x = h2pack(slotW(Wr, p0, 0), slotW(Wr, p0, 1));
        w.y = h2pack(slotW(Wr, p2, 0), slotW(Wr, p2, 1));
        BQ2[lg * B_LG_STRIDE + kb * 8 + nb] = w;
    }

    // ---- fp32 time-weight + bias pairs ----
    if (tid < 32) {
        wb4[tid] = make_float4(W[(size_t)(2 * tid) * 316], bvec[2 * tid],
                               W[(size_t)(2 * tid + 1) * 316], bvec[2 * tid + 1]);
    }
    __syncthreads();

    // ---- mainloop ----
    const int q4 = lane >> 2;
    const int s4 = lane & 3;
    const int rowa = wid * 16 + q4;            // 0..247

    // per-thread base word offsets
    const int bxp0 = XP_OFF + (rowa + 2 * (s4 & 1)) * XPS + (s4 >> 1) + 1;
    const int bxp1 = bxp0 + 8 * XPS;
    const int bxr0 = XR_OFF + (rowa + 4) * XRS + s4 - 126;
    const int bxr1 = bxr0 + 8 * XRS;
    const int ub   = (q4 * 4 + s4) * B_LG_STRIDE;

    float d[8][4];
#pragma unroll
    for (int nb = 0; nb < 8; nb++) { d[nb][0] = d[nb][1] = d[nb][2] = d[nb][3] = 0.f; }

#pragma unroll
    for (int kb = 0; kb < 20; kb++) {
        int A0, A1, A2, A3;
        if (kb <= 14) {
            A0 = bxp0 + 4 * kb; A1 = bxp1 + 4 * kb; A2 = A0 + 2; A3 = A1 + 2;
        } else if (kb == 15) {
            A0 = bxp0 + 60; A1 = bxp1 + 60;
            A2 = (s4 < 2) ? (bxp0 + 62) : (bxr0 + 124);
            A3 = (s4 < 2) ? (bxp1 + 62) : (bxr1 + 124);
        } else if (kb <= 18) {
            A0 = bxr0 + 8 * kb; A1 = bxr1 + 8 * kb; A2 = A0 + 4; A3 = A1 + 4;
        } else {
            A0 = bxr0 + 152; A1 = bxr1 + 152;
            A2 = (s4 < 2) ? (bxr0 + 156) : ZW_OFF;
            A3 = (s4 < 2) ? (bxr1 + 156) : ZW_OFF;
        }
        uint32_t a[4];
        a[0] = sm[A0]; a[1] = sm[A1]; a[2] = sm[A2]; a[3] = sm[A3];
#pragma unroll
        for (int nb = 0; nb < 8; nb++) {
            uint2 b = BQ2[ub + kb * 8 + nb];
            mma_f16(d[nb], a, b.x, b.y);
        }
    }

    // ---- epilogue: + W[:,0]*t_resc + b, Lorentz norm, store ----
    const float tra = tr[rowa];
    const float trb = tr[rowa + 8];
    float ssa = 0.f, ssb = 0.f;
#pragma unroll
    for (int nb = 0; nb < 8; nb++) {
        float4 f4 = wb4[nb * 4 + s4];
        float y0 = fmaf(f4.x, tra, d[nb][0]) + f4.y;
        float y1 = fmaf(f4.z, tra, d[nb][1]) + f4.w;
        float y2 = fmaf(f4.x, trb, d[nb][2]) + f4.y;
        float y3 = fmaf(f4.z, trb, d[nb][3]) + f4.w;
        if (!(nb == 0 && s4 == 0)) {           // col 0 excluded from the norm
            ssa = fmaf(y0, y0, ssa);
            ssb = fmaf(y2, y2, ssb);
        }
        ssa = fmaf(y1, y1, ssa);
        ssb = fmaf(y3, y3, ssb);
        d[nb][0] = y0; d[nb][1] = y1; d[nb][2] = y2; d[nb][3] = y3;
    }
    ssa += __shfl_xor_sync(0xffffffffu, ssa, 1);
    ssa += __shfl_xor_sync(0xffffffffu, ssa, 2);
    ssb += __shfl_xor_sync(0xffffffffu, ssb, 1);
    ssb += __shfl_xor_sync(0xffffffffu, ssb, 2);
    if (s4 == 0) {
        d[0][0] = sqrtf(ssa + 1.0f);
        d[0][2] = sqrtf(ssb + 1.0f);
    }

    const size_t oa = ((size_t)bidx * LLEN + (size_t)(l0 + rowa)) * 64 + 2 * s4;
    const size_t ob = oa + 8 * 64;
#pragma unroll
    for (int nb = 0; nb < 8; nb++) {
        *(float2*)(out + oa + nb * 8) = make_float2(d[nb][0], d[nb][1]);
        *(float2*)(out + ob + nb * 8) = make_float2(d[nb][2], d[nb][3]);
    }
}

extern "C" void kernel_launch(void* const* d_in, const int* in_sizes, int n_in,
                              void* d_out, int out_size)
{
    const float* x = (const float*)d_in[0];
    const float* W = (const float*)d_in[1];
    const float* b = (const float*)d_in[2];
    float* out = (float*)d_out;

    cudaFuncSetAttribute(lorentz_f16_kernel,
                         cudaFuncAttributeMaxDynamicSharedMemorySize, SMEM_BYTES);
    lorentz_f16_kernel<<<512, 512, SMEM_BYTES>>>(x, W, b, out);
}